// round 15
// baseline (speedup 1.0000x reference)
#include <cuda_runtime.h>
#include <cuda_pipeline.h>
#include <stdint.h>

// Problem constants
#define NB    32
#define CIN   256
#define HH    56
#define WW    56
#define COUT  256
#define HW    3136
#define MTOT  100352              // 32*3136
#define NWORD 8
#define WPAD  58
#define BN_EPS 1e-5f

// M partition: IMMA takes first 65408 pixels (511 tiles), popcount last 624 rows
#define PC_BLOCKS   624
#define IMMA_BLOCKS 1022          // 511 M-tiles x 2 cout-halves
#define PC_ROW0     1168          // 65408 / 56

// IMMA mainloop config (verbatim R14)
#define NSTEP 18
#define ROWB    144
#define STG_A   18432
#define STG_SZ  36864
#define EPI_STRIDE 129
#define SMEM_DYN (3 * STG_SZ)     // 110592

// Scratch (no allocations)
__device__ __align__(16) int8_t   g_xs[(size_t)MTOT * CIN];      // NHWC int8 signs
__device__ __align__(16) int8_t   g_ws[(size_t)COUT * 9 * CIN];  // [co][tap][ci]
__device__ uint32_t g_xp[(size_t)NWORD * MTOT];                  // bitplanes [wd][pix]
__device__ uint32_t g_wp[9 * NWORD * COUT];                      // [tap][word][co]

__device__ __forceinline__ uint32_t smem_u32(const void* p) {
    uint32_t a;
    asm("{ .reg .u64 t; cvta.to.shared.u64 t, %1; cvt.u32.u64 %0, t; }"
        : "=r"(a) : "l"(p));
    return a;
}

// ---------------------------------------------------------------------------
// Combined x pack: int8 NHWC (g_xs) + bitplanes (g_xp), one read of x.
// ---------------------------------------------------------------------------
__global__ void pack_xcomb_kernel(const float* __restrict__ x) {
    int b = blockIdx.x;            // n*56 + h
    int n = b / HH, h = b % HH;
    int t = threadIdx.x;
    if (t >= WW * 8) return;
    int wd = t / WW;               // ci block of 32
    int w  = t % WW;
    const float* xb = x + ((size_t)n * CIN + (size_t)wd * 32) * HW + (size_t)h * WW + w;
    uint32_t wv[8];
    uint32_t bits = 0;
    #pragma unroll
    for (int j = 0; j < 8; ++j) {
        uint32_t acc = 0;
        #pragma unroll
        for (int c = 0; c < 4; ++c) {
            float v = __ldg(xb + (size_t)(j * 4 + c) * HW);
            bool pos = (v > 0.0f);
            acc |= (pos ? 0x01u : 0xFFu) << (8 * c);
            bits |= (pos ? 1u : 0u) << (4 * j + c);
        }
        wv[j] = acc;
    }
    size_t pix = (size_t)b * WW + w;
    uint4* dst = (uint4*)(g_xs + pix * CIN + wd * 32);
    dst[0] = make_uint4(wv[0], wv[1], wv[2], wv[3]);
    dst[1] = make_uint4(wv[4], wv[5], wv[6], wv[7]);
    g_xp[(size_t)wd * MTOT + pix] = bits;       // coalesced (consecutive w)
}

// ---------------------------------------------------------------------------
__global__ void pack_ws_kernel(const float* __restrict__ wt) {
    int idx = blockIdx.x * 256 + threadIdx.x;
    int co = idx / (9 * CIN);
    int r  = idx - co * (9 * CIN);
    int tap = r >> 8, ci = r & 255;
    float v = __ldg(wt + ((size_t)co * CIN + ci) * 9 + tap);
    g_ws[idx] = (v > 0.0f) ? (int8_t)1 : (int8_t)-1;
}

__global__ void pack_wp_kernel(const float* __restrict__ wt) {
    int gid = blockIdx.x * blockDim.x + threadIdx.x;
    if (gid >= 9 * NWORD * COUT) return;
    int co  = gid & 255;
    int tw  = gid >> 8;
    int tap = tw >> 3, wd = tw & 7;
    const float* wb = wt + ((size_t)co * CIN + (size_t)wd * 32) * 9 + tap;
    uint32_t bits = 0;
    #pragma unroll
    for (int c = 0; c < 32; ++c)
        bits |= (__ldg(wb + c * 9) > 0.0f) ? (1u << c) : 0u;
    g_wp[gid] = bits;
}

// ---------------------------------------------------------------------------
// Popcount body (R6-verified): rows PC_ROW0..1791, thread = co.
// ---------------------------------------------------------------------------
__device__ __forceinline__ void popcount_body(
    char* sm, int row,
    const float* gamma, const float* beta,
    const float* rmean, const float* rvar, float* out)
{
    uint32_t* xs = (uint32_t*)sm;               // [3][WPAD*NWORD]
    int n = row / HH, h = row % HH;
    int t = threadIdx.x;

    uint32_t wreg[9][NWORD];
    #pragma unroll
    for (int tap = 0; tap < 9; ++tap)
        #pragma unroll
        for (int wd = 0; wd < NWORD; ++wd)
            wreg[tap][wd] = g_wp[(tap * NWORD + wd) * COUT + t];

    int m[9];
    #pragma unroll
    for (int tap = 0; tap < 9; ++tap) {
        int pw = 0;
        #pragma unroll
        for (int wd = 0; wd < NWORD; ++wd) pw += __popc(wreg[tap][wd]);
        m[tap] = 256 - pw;
    }

    bool r0 = (h > 0), r2 = (h < HH - 1);
    bool rowok[3] = { r0, true, r2 };
    #pragma unroll
    for (int kh = 0; kh < 3; ++kh) {
        uint32_t* xrow = xs + kh * (WPAD * NWORD);
        if (rowok[kh]) {
            if (t < 2 * NWORD) {
                int c = (t < NWORD) ? 0 : (WPAD - 1);
                xrow[c * NWORD + (t & 7)] = 0u;
            }
            int rp = (n * HH + (h + kh - 1)) * WW;
            for (int i = t; i < WW * NWORD; i += 256) {
                int wd = i / WW, w = i % WW;
                xrow[(w + 1) * NWORD + wd] = g_xp[(size_t)wd * MTOT + rp + w];
            }
        } else {
            for (int i = t; i < WPAD * NWORD; i += 256) xrow[i] = 0u;
        }
    }
    __syncthreads();

    float iv = gamma[t] * rsqrtf(rvar[t] + BN_EPS);
    float bs = fmaf(-rmean[t], iv, beta[t]);
    int rowcnt    = (int)r0 + 1 + (int)r2;
    int Minv_base = (r0 ? 0 : (m[0] + m[1] + m[2])) + (r2 ? 0 : (m[6] + m[7] + m[8]));
    int Mleft     = (r0 ? m[0] : 0) + m[3] + (r2 ? m[6] : 0);
    int Mright    = (r0 ? m[2] : 0) + m[5] + (r2 ? m[8] : 0);
    int nv_base   = 3 * rowcnt;
    float niv2    = -2.0f * iv;
    float c_mid   = fmaf((float)(4608 - 2 * Minv_base - 256 * nv_base), iv, bs);
    float c_left  = fmaf((float)(4608 - 2 * (Minv_base + Mleft)  - 256 * (nv_base - rowcnt)), iv, bs);
    float c_right = fmaf((float)(4608 - 2 * (Minv_base + Mright) - 256 * (nv_base - rowcnt)), iv, bs);

    float* op = out + (((size_t)n * COUT + t) * HH + h) * WW;
    #pragma unroll 2
    for (int w = 0; w < WW; ++w) {
        int accx = 0;
        #pragma unroll
        for (int kh = 0; kh < 3; ++kh) {
            #pragma unroll
            for (int kw = 0; kw < 3; ++kw) {
                const uint4* p = (const uint4*)(xs + kh * (WPAD * NWORD) + (w + kw) * NWORD);
                uint4 a = p[0], c = p[1];
                const uint32_t* wr = wreg[kh * 3 + kw];
                accx += __popc(a.x ^ wr[0]) + __popc(a.y ^ wr[1])
                      + __popc(a.z ^ wr[2]) + __popc(a.w ^ wr[3])
                      + __popc(c.x ^ wr[4]) + __popc(c.y ^ wr[5])
                      + __popc(c.z ^ wr[6]) + __popc(c.w ^ wr[7]);
            }
        }
        float cb = c_mid;
        if (w == 0)      cb = c_left;
        if (w == WW - 1) cb = c_right;
        op[w] = fmaf((float)accx, niv2, cb);
    }
}

// ---------------------------------------------------------------------------
// IMMA body (R14-verified): pixels [0, 65408), tiles of 128x128.
// ---------------------------------------------------------------------------
__device__ __forceinline__ void imma_body(
    char* sm, int ib,
    const float* gamma, const float* beta,
    const float* rmean, const float* rvar, float* out)
{
    __shared__ float ivs[128], bss[128];
    int tid = threadIdx.x, lane = tid & 31, wid = tid >> 5;
    int mb  = (ib >> 1) * 128;
    int cob = (ib & 1) * 128;
    uint32_t smb = smem_u32(sm);

    if (tid < 128) {
        int co = cob + tid;
        float iv = gamma[co] * rsqrtf(rvar[co] + BN_EPS);
        ivs[tid] = iv;
        bss[tid] = fmaf(-rmean[co], iv, beta[co]);
    }

    int srow = tid >> 1, shalf = tid & 1;
    int am = mb + srow;
    int an = am / HW; int ahw = am - an * HW;
    int ah = ahw / WW, aw = ahw - ah * WW;
    const int8_t* axbase = g_xs + (size_t)an * HW * CIN;
    const int8_t* bwrow  = g_ws + (size_t)(cob + srow) * 9 * CIN;

#define STAGEOP(s) do {                                                       \
    int tap = (s) >> 1;                                                       \
    int ci0 = ((s) & 1) * 128 + shalf * 64;                                   \
    int dh = tap / 3 - 1, dw = tap - (tap / 3) * 3 - 1;                       \
    int hp = ah + dh, wp = aw + dw;                                           \
    bool okp = ((unsigned)hp < (unsigned)HH && (unsigned)wp < (unsigned)WW);  \
    int hc = hp < 0 ? 0 : (hp > 55 ? 55 : hp);                                \
    int wc = wp < 0 ? 0 : (wp > 55 ? 55 : wp);                                \
    const int8_t* ga = axbase + (size_t)(hc * WW + wc) * CIN + ci0;           \
    char* ad = sm + ((s) % 3) * STG_SZ + srow * ROWB + shalf * 64;            \
    size_t zf = okp ? 0 : 16;                                                 \
    __pipeline_memcpy_async(ad,      ga,      16, zf);                        \
    __pipeline_memcpy_async(ad + 16, ga + 16, 16, zf);                        \
    __pipeline_memcpy_async(ad + 32, ga + 32, 16, zf);                        \
    __pipeline_memcpy_async(ad + 48, ga + 48, 16, zf);                        \
    const int8_t* gb = bwrow + (size_t)tap * CIN + ci0;                       \
    char* bd = sm + ((s) % 3) * STG_SZ + STG_A + srow * ROWB + shalf * 64;    \
    __pipeline_memcpy_async(bd,      gb,      16, 0);                         \
    __pipeline_memcpy_async(bd + 16, gb + 16, 16, 0);                         \
    __pipeline_memcpy_async(bd + 32, gb + 32, 16, 0);                        \
    __pipeline_memcpy_async(bd + 48, gb + 48, 16, 0);                         \
} while (0)

    int g = lane >> 2, q = lane & 3;
    int warp_m = (wid & 3) * 32, warp_n = (wid >> 2) * 64;
    uint32_t aoff = (uint32_t)((warp_m + (lane & 15)) * ROWB + (lane >> 4) * 16);
    uint32_t boff = (uint32_t)((warp_n + (lane & 7) + ((lane >> 4) << 3)) * ROWB
                               + ((lane >> 3) & 1) * 16);

    int acc[2][8][4];
    #pragma unroll
    for (int i = 0; i < 2; ++i)
        #pragma unroll
        for (int j = 0; j < 8; ++j)
            #pragma unroll
            for (int k = 0; k < 4; ++k) acc[i][j][k] = 0;

    STAGEOP(0); __pipeline_commit();
    STAGEOP(1); __pipeline_commit();

    for (int s = 0; s < NSTEP; ++s) {
        __pipeline_wait_prior(1);
        __syncthreads();
        if (s + 2 < NSTEP) STAGEOP(s + 2);      // safe: target buf idle this iter
        __pipeline_commit();

        uint32_t abase = smb + (s % 3) * STG_SZ;
        uint32_t bbase = abase + STG_A;

        #pragma unroll
        for (int kc = 0; kc < 4; ++kc) {
            uint32_t A[2][4], B[8][2];
            #pragma unroll
            for (int ma = 0; ma < 2; ++ma) {
                uint32_t addr = abase + aoff + ma * 16 * ROWB + kc * 32;
                asm volatile(
                    "ldmatrix.sync.aligned.m8n8.x4.shared.b16 {%0,%1,%2,%3}, [%4];"
                    : "=r"(A[ma][0]), "=r"(A[ma][1]), "=r"(A[ma][2]), "=r"(A[ma][3])
                    : "r"(addr));
            }
            #pragma unroll
            for (int nb = 0; nb < 4; ++nb) {
                uint32_t addr = bbase + boff + nb * 16 * ROWB + kc * 32;
                asm volatile(
                    "ldmatrix.sync.aligned.m8n8.x4.shared.b16 {%0,%1,%2,%3}, [%4];"
                    : "=r"(B[2 * nb][0]), "=r"(B[2 * nb][1]),
                      "=r"(B[2 * nb + 1][0]), "=r"(B[2 * nb + 1][1])
                    : "r"(addr));
            }
            #pragma unroll
            for (int ma = 0; ma < 2; ++ma)
                #pragma unroll
                for (int na = 0; na < 8; ++na)
                    asm volatile(
                        "mma.sync.aligned.m16n8k32.row.col.s32.s8.s8.s32 "
                        "{%0,%1,%2,%3}, {%4,%5,%6,%7}, {%8,%9}, {%0,%1,%2,%3};"
                        : "+r"(acc[ma][na][0]), "+r"(acc[ma][na][1]),
                          "+r"(acc[ma][na][2]), "+r"(acc[ma][na][3])
                        : "r"(A[ma][0]), "r"(A[ma][1]), "r"(A[ma][2]), "r"(A[ma][3]),
                          "r"(B[na][0]), "r"(B[na][1]));
        }
    }

    __pipeline_wait_prior(0);
    __syncthreads();

    float* epi = (float*)sm;
    #pragma unroll
    for (int ma = 0; ma < 2; ++ma) {
        int m0 = warp_m + ma * 16 + g;
        #pragma unroll
        for (int na = 0; na < 8; ++na) {
            int c0 = warp_n + na * 8 + 2 * q;
            epi[(c0    ) * EPI_STRIDE + m0    ] = fmaf((float)acc[ma][na][0], ivs[c0],     bss[c0]);
            epi[(c0 + 1) * EPI_STRIDE + m0    ] = fmaf((float)acc[ma][na][1], ivs[c0 + 1], bss[c0 + 1]);
            epi[(c0    ) * EPI_STRIDE + m0 + 8] = fmaf((float)acc[ma][na][2], ivs[c0],     bss[c0]);
            epi[(c0 + 1) * EPI_STRIDE + m0 + 8] = fmaf((float)acc[ma][na][3], ivs[c0 + 1], bss[c0 + 1]);
        }
    }
    __syncthreads();

    for (int cc = 0; cc < 16; ++cc) {
        int col = wid + cc * 8;
        size_t cog = cob + col;
        #pragma unroll
        for (int mmi = 0; mmi < 4; ++mmi) {
            int ml = mmi * 32 + lane;
            int m  = mb + ml;
            int n2 = m / HW; int hw = m - n2 * HW;
            out[(size_t)n2 * COUT * HW + cog * HW + hw] = epi[col * EPI_STRIDE + ml];
        }
    }
}

// ---------------------------------------------------------------------------
// Hybrid: popcount blocks first (alu pipe), IMMA blocks after (tensor pipe).
// ---------------------------------------------------------------------------
__global__ void __launch_bounds__(256, 2)
conv_hybrid_kernel(const float* __restrict__ gamma, const float* __restrict__ beta,
                   const float* __restrict__ rmean, const float* __restrict__ rvar,
                   float* __restrict__ out) {
    extern __shared__ char sm[];
    if (blockIdx.x < PC_BLOCKS)
        popcount_body(sm, PC_ROW0 + blockIdx.x, gamma, beta, rmean, rvar, out);
    else
        imma_body(sm, blockIdx.x - PC_BLOCKS, gamma, beta, rmean, rvar, out);
}

// ---------------------------------------------------------------------------
extern "C" void kernel_launch(void* const* d_in, const int* in_sizes, int n_in,
                              void* d_out, int out_size) {
    const float* x     = (const float*)d_in[0];
    const float* wt    = (const float*)d_in[1];
    const float* gamma = (const float*)d_in[2];
    const float* beta  = (const float*)d_in[3];
    const float* rmean = (const float*)d_in[4];
    const float* rvar  = (const float*)d_in[5];
    float* out = (float*)d_out;

    cudaFuncSetAttribute(conv_hybrid_kernel,
                         cudaFuncAttributeMaxDynamicSharedMemorySize, SMEM_DYN);

    pack_xcomb_kernel<<<NB * HH, 512>>>(x);
    pack_ws_kernel<<<9 * COUT, 256>>>(wt);
    pack_wp_kernel<<<72, 256>>>(wt);
    conv_hybrid_kernel<<<PC_BLOCKS + IMMA_BLOCKS, 256, SMEM_DYN>>>(
        gamma, beta, rmean, rvar, out);
}

// round 16
// speedup vs baseline: 1.0690x; 1.0690x over previous
#include <cuda_runtime.h>
#include <cuda_pipeline.h>
#include <stdint.h>

// Problem constants
#define NB    32
#define CIN   256
#define HH    56
#define WW    56
#define COUT  256
#define HW    3136
#define MTOT  100352              // 32*3136
#define NWORD 8
#define WPAD  58
#define BN_EPS 1e-5f

// M partition: IMMA first 65408 pixels (1022 blocks), popcount last 624 rows
#define PC_BLOCKS   624
#define IMMA_BLOCKS 1022
#define PC_ROW0     1168          // 65408 / 56

// IMMA mainloop config (verbatim R14)
#define NSTEP 18
#define ROWB    144
#define STG_A   18432
#define STG_SZ  36864
#define EPI_STRIDE 129
#define SMEM_DYN (3 * STG_SZ)     // 110592

// Scratch (no allocations)
__device__ __align__(16) int8_t   g_xs[(size_t)MTOT * CIN];      // NHWC int8 signs
__device__ __align__(16) int8_t   g_ws[(size_t)COUT * 9 * CIN];  // [co][tap][ci]
__device__ uint32_t g_xp[(size_t)NWORD * MTOT];                  // bitplanes [wd][pix]
__device__ uint32_t g_wp[9 * NWORD * COUT];                      // [tap][word][co]

__device__ __forceinline__ uint32_t smem_u32(const void* p) {
    uint32_t a;
    asm("{ .reg .u64 t; cvta.to.shared.u64 t, %1; cvt.u32.u64 %0, t; }"
        : "=r"(a) : "l"(p));
    return a;
}

// ---------------------------------------------------------------------------
// Combined x pack: int8 NHWC (g_xs) + bitplanes (g_xp), one read of x.
// ---------------------------------------------------------------------------
__global__ void pack_xcomb_kernel(const float* __restrict__ x) {
    int b = blockIdx.x;            // n*56 + h
    int n = b / HH, h = b % HH;
    int t = threadIdx.x;
    if (t >= WW * 8) return;
    int wd = t / WW;               // ci block of 32
    int w  = t % WW;
    const float* xb = x + ((size_t)n * CIN + (size_t)wd * 32) * HW + (size_t)h * WW + w;
    uint32_t wv[8];
    uint32_t bits = 0;
    #pragma unroll
    for (int j = 0; j < 8; ++j) {
        uint32_t acc = 0;
        #pragma unroll
        for (int c = 0; c < 4; ++c) {
            float v = __ldg(xb + (size_t)(j * 4 + c) * HW);
            bool pos = (v > 0.0f);
            acc |= (pos ? 0x01u : 0xFFu) << (8 * c);
            bits |= (pos ? 1u : 0u) << (4 * j + c);
        }
        wv[j] = acc;
    }
    size_t pix = (size_t)b * WW + w;
    uint4* dst = (uint4*)(g_xs + pix * CIN + wd * 32);
    dst[0] = make_uint4(wv[0], wv[1], wv[2], wv[3]);
    dst[1] = make_uint4(wv[4], wv[5], wv[6], wv[7]);
    g_xp[(size_t)wd * MTOT + pix] = bits;       // coalesced (consecutive w)
}

// ---------------------------------------------------------------------------
__global__ void pack_ws_kernel(const float* __restrict__ wt) {
    int idx = blockIdx.x * 256 + threadIdx.x;
    int co = idx / (9 * CIN);
    int r  = idx - co * (9 * CIN);
    int tap = r >> 8, ci = r & 255;
    float v = __ldg(wt + ((size_t)co * CIN + ci) * 9 + tap);
    g_ws[idx] = (v > 0.0f) ? (int8_t)1 : (int8_t)-1;
}

__global__ void pack_wp_kernel(const float* __restrict__ wt) {
    int gid = blockIdx.x * blockDim.x + threadIdx.x;
    if (gid >= 9 * NWORD * COUT) return;
    int co  = gid & 255;
    int tw  = gid >> 8;
    int tap = tw >> 3, wd = tw & 7;
    const float* wb = wt + ((size_t)co * CIN + (size_t)wd * 32) * 9 + tap;
    uint32_t bits = 0;
    #pragma unroll
    for (int c = 0; c < 32; ++c)
        bits |= (__ldg(wb + c * 9) > 0.0f) ? (1u << c) : 0u;
    g_wp[gid] = bits;
}

// ---------------------------------------------------------------------------
// Popcount body (R6-verified): rows PC_ROW0..1791, thread = co.
// ---------------------------------------------------------------------------
__device__ __forceinline__ void popcount_body(
    char* sm, int row,
    const float* gamma, const float* beta,
    const float* rmean, const float* rvar, float* out)
{
    uint32_t* xs = (uint32_t*)sm;               // [3][WPAD*NWORD]
    int n = row / HH, h = row % HH;
    int t = threadIdx.x;

    uint32_t wreg[9][NWORD];
    #pragma unroll
    for (int tap = 0; tap < 9; ++tap)
        #pragma unroll
        for (int wd = 0; wd < NWORD; ++wd)
            wreg[tap][wd] = g_wp[(tap * NWORD + wd) * COUT + t];

    int m[9];
    #pragma unroll
    for (int tap = 0; tap < 9; ++tap) {
        int pw = 0;
        #pragma unroll
        for (int wd = 0; wd < NWORD; ++wd) pw += __popc(wreg[tap][wd]);
        m[tap] = 256 - pw;
    }

    bool r0 = (h > 0), r2 = (h < HH - 1);
    bool rowok[3] = { r0, true, r2 };
    #pragma unroll
    for (int kh = 0; kh < 3; ++kh) {
        uint32_t* xrow = xs + kh * (WPAD * NWORD);
        if (rowok[kh]) {
            if (t < 2 * NWORD) {
                int c = (t < NWORD) ? 0 : (WPAD - 1);
                xrow[c * NWORD + (t & 7)] = 0u;
            }
            int rp = (n * HH + (h + kh - 1)) * WW;
            for (int i = t; i < WW * NWORD; i += 256) {
                int wd = i / WW, w = i % WW;
                xrow[(w + 1) * NWORD + wd] = g_xp[(size_t)wd * MTOT + rp + w];
            }
        } else {
            for (int i = t; i < WPAD * NWORD; i += 256) xrow[i] = 0u;
        }
    }
    __syncthreads();

    float iv = gamma[t] * rsqrtf(rvar[t] + BN_EPS);
    float bs = fmaf(-rmean[t], iv, beta[t]);
    int rowcnt    = (int)r0 + 1 + (int)r2;
    int Minv_base = (r0 ? 0 : (m[0] + m[1] + m[2])) + (r2 ? 0 : (m[6] + m[7] + m[8]));
    int Mleft     = (r0 ? m[0] : 0) + m[3] + (r2 ? m[6] : 0);
    int Mright    = (r0 ? m[2] : 0) + m[5] + (r2 ? m[8] : 0);
    int nv_base   = 3 * rowcnt;
    float niv2    = -2.0f * iv;
    float c_mid   = fmaf((float)(4608 - 2 * Minv_base - 256 * nv_base), iv, bs);
    float c_left  = fmaf((float)(4608 - 2 * (Minv_base + Mleft)  - 256 * (nv_base - rowcnt)), iv, bs);
    float c_right = fmaf((float)(4608 - 2 * (Minv_base + Mright) - 256 * (nv_base - rowcnt)), iv, bs);

    float* op = out + (((size_t)n * COUT + t) * HH + h) * WW;
    #pragma unroll 2
    for (int w = 0; w < WW; ++w) {
        int accx = 0;
        #pragma unroll
        for (int kh = 0; kh < 3; ++kh) {
            #pragma unroll
            for (int kw = 0; kw < 3; ++kw) {
                const uint4* p = (const uint4*)(xs + kh * (WPAD * NWORD) + (w + kw) * NWORD);
                uint4 a = p[0], c = p[1];
                const uint32_t* wr = wreg[kh * 3 + kw];
                accx += __popc(a.x ^ wr[0]) + __popc(a.y ^ wr[1])
                      + __popc(a.z ^ wr[2]) + __popc(a.w ^ wr[3])
                      + __popc(c.x ^ wr[4]) + __popc(c.y ^ wr[5])
                      + __popc(c.z ^ wr[6]) + __popc(c.w ^ wr[7]);
            }
        }
        float cb = c_mid;
        if (w == 0)      cb = c_left;
        if (w == WW - 1) cb = c_right;
        op[w] = fmaf((float)accx, niv2, cb);
    }
}

// ---------------------------------------------------------------------------
// IMMA body (R14-verified): pixels [0, 65408), tiles of 128x128.
// ---------------------------------------------------------------------------
__device__ __forceinline__ void imma_body(
    char* sm, int ib,
    const float* gamma, const float* beta,
    const float* rmean, const float* rvar, float* out)
{
    __shared__ float ivs[128], bss[128];
    int tid = threadIdx.x, lane = tid & 31, wid = tid >> 5;
    int mb  = (ib >> 1) * 128;
    int cob = (ib & 1) * 128;
    uint32_t smb = smem_u32(sm);

    if (tid < 128) {
        int co = cob + tid;
        float iv = gamma[co] * rsqrtf(rvar[co] + BN_EPS);
        ivs[tid] = iv;
        bss[tid] = fmaf(-rmean[co], iv, beta[co]);
    }

    int srow = tid >> 1, shalf = tid & 1;
    int am = mb + srow;
    int an = am / HW; int ahw = am - an * HW;
    int ah = ahw / WW, aw = ahw - ah * WW;
    const int8_t* axbase = g_xs + (size_t)an * HW * CIN;
    const int8_t* bwrow  = g_ws + (size_t)(cob + srow) * 9 * CIN;

#define STAGEOP(s) do {                                                       \
    int tap = (s) >> 1;                                                       \
    int ci0 = ((s) & 1) * 128 + shalf * 64;                                   \
    int dh = tap / 3 - 1, dw = tap - (tap / 3) * 3 - 1;                       \
    int hp = ah + dh, wp = aw + dw;                                           \
    bool okp = ((unsigned)hp < (unsigned)HH && (unsigned)wp < (unsigned)WW);  \
    int hc = hp < 0 ? 0 : (hp > 55 ? 55 : hp);                                \
    int wc = wp < 0 ? 0 : (wp > 55 ? 55 : wp);                                \
    const int8_t* ga = axbase + (size_t)(hc * WW + wc) * CIN + ci0;           \
    char* ad = sm + ((s) % 3) * STG_SZ + srow * ROWB + shalf * 64;            \
    size_t zf = okp ? 0 : 16;                                                 \
    __pipeline_memcpy_async(ad,      ga,      16, zf);                        \
    __pipeline_memcpy_async(ad + 16, ga + 16, 16, zf);                        \
    __pipeline_memcpy_async(ad + 32, ga + 32, 16, zf);                        \
    __pipeline_memcpy_async(ad + 48, ga + 48, 16, zf);                        \
    const int8_t* gb = bwrow + (size_t)tap * CIN + ci0;                       \
    char* bd = sm + ((s) % 3) * STG_SZ + STG_A + srow * ROWB + shalf * 64;    \
    __pipeline_memcpy_async(bd,      gb,      16, 0);                         \
    __pipeline_memcpy_async(bd + 16, gb + 16, 16, 0);                         \
    __pipeline_memcpy_async(bd + 32, gb + 32, 16, 0);                         \
    __pipeline_memcpy_async(bd + 48, gb + 48, 16, 0);                         \
} while (0)

    int g = lane >> 2, q = lane & 3;
    int warp_m = (wid & 3) * 32, warp_n = (wid >> 2) * 64;
    uint32_t aoff = (uint32_t)((warp_m + (lane & 15)) * ROWB + (lane >> 4) * 16);
    uint32_t boff = (uint32_t)((warp_n + (lane & 7) + ((lane >> 4) << 3)) * ROWB
                               + ((lane >> 3) & 1) * 16);

    int acc[2][8][4];
    #pragma unroll
    for (int i = 0; i < 2; ++i)
        #pragma unroll
        for (int j = 0; j < 8; ++j)
            #pragma unroll
            for (int k = 0; k < 4; ++k) acc[i][j][k] = 0;

    STAGEOP(0); __pipeline_commit();
    STAGEOP(1); __pipeline_commit();

    for (int s = 0; s < NSTEP; ++s) {
        __pipeline_wait_prior(1);
        __syncthreads();
        if (s + 2 < NSTEP) STAGEOP(s + 2);      // target buf idle this iter
        __pipeline_commit();

        uint32_t abase = smb + (s % 3) * STG_SZ;
        uint32_t bbase = abase + STG_A;

        #pragma unroll
        for (int kc = 0; kc < 4; ++kc) {
            uint32_t A[2][4], B[8][2];
            #pragma unroll
            for (int ma = 0; ma < 2; ++ma) {
                uint32_t addr = abase + aoff + ma * 16 * ROWB + kc * 32;
                asm volatile(
                    "ldmatrix.sync.aligned.m8n8.x4.shared.b16 {%0,%1,%2,%3}, [%4];"
                    : "=r"(A[ma][0]), "=r"(A[ma][1]), "=r"(A[ma][2]), "=r"(A[ma][3])
                    : "r"(addr));
            }
            #pragma unroll
            for (int nb = 0; nb < 4; ++nb) {
                uint32_t addr = bbase + boff + nb * 16 * ROWB + kc * 32;
                asm volatile(
                    "ldmatrix.sync.aligned.m8n8.x4.shared.b16 {%0,%1,%2,%3}, [%4];"
                    : "=r"(B[2 * nb][0]), "=r"(B[2 * nb][1]),
                      "=r"(B[2 * nb + 1][0]), "=r"(B[2 * nb + 1][1])
                    : "r"(addr));
            }
            #pragma unroll
            for (int ma = 0; ma < 2; ++ma)
                #pragma unroll
                for (int na = 0; na < 8; ++na)
                    asm volatile(
                        "mma.sync.aligned.m16n8k32.row.col.s32.s8.s8.s32 "
                        "{%0,%1,%2,%3}, {%4,%5,%6,%7}, {%8,%9}, {%0,%1,%2,%3};"
                        : "+r"(acc[ma][na][0]), "+r"(acc[ma][na][1]),
                          "+r"(acc[ma][na][2]), "+r"(acc[ma][na][3])
                        : "r"(A[ma][0]), "r"(A[ma][1]), "r"(A[ma][2]), "r"(A[ma][3]),
                          "r"(B[na][0]), "r"(B[na][1]));
        }
    }

    __pipeline_wait_prior(0);
    __syncthreads();

    float* epi = (float*)sm;
    #pragma unroll
    for (int ma = 0; ma < 2; ++ma) {
        int m0 = warp_m + ma * 16 + g;
        #pragma unroll
        for (int na = 0; na < 8; ++na) {
            int c0 = warp_n + na * 8 + 2 * q;
            epi[(c0    ) * EPI_STRIDE + m0    ] = fmaf((float)acc[ma][na][0], ivs[c0],     bss[c0]);
            epi[(c0 + 1) * EPI_STRIDE + m0    ] = fmaf((float)acc[ma][na][1], ivs[c0 + 1], bss[c0 + 1]);
            epi[(c0    ) * EPI_STRIDE + m0 + 8] = fmaf((float)acc[ma][na][2], ivs[c0],     bss[c0]);
            epi[(c0 + 1) * EPI_STRIDE + m0 + 8] = fmaf((float)acc[ma][na][3], ivs[c0 + 1], bss[c0 + 1]);
        }
    }
    __syncthreads();

    for (int cc = 0; cc < 16; ++cc) {
        int col = wid + cc * 8;
        size_t cog = cob + col;
        #pragma unroll
        for (int mmi = 0; mmi < 4; ++mmi) {
            int ml = mmi * 32 + lane;
            int m  = mb + ml;
            int n2 = m / HW; int hw = m - n2 * HW;
            out[(size_t)n2 * COUT * HW + cog * HW + hw] = epi[col * EPI_STRIDE + ml];
        }
    }
}

// ---------------------------------------------------------------------------
// Hybrid with WAVE-INTERLEAVED flavors: alternate chunks of 148 blocks so each
// SM holds one popcount CTA (alu pipe) + one IMMA CTA (tensor pipe).
// chunks 0,2,4,6 -> imma (592), chunks 1,3,5,7 -> pc (592),
// then 32 pc + 430 imma tail.
// ---------------------------------------------------------------------------
__global__ void __launch_bounds__(256, 2)
conv_hybrid_kernel(const float* __restrict__ gamma, const float* __restrict__ beta,
                   const float* __restrict__ rmean, const float* __restrict__ rvar,
                   float* __restrict__ out) {
    extern __shared__ char sm[];
    int idx = blockIdx.x;
    int flavor, sub;
    if (idx < 1184) {
        int chunk = idx / 148, within = idx - chunk * 148;
        flavor = chunk & 1;
        sub = (chunk >> 1) * 148 + within;
    } else {
        int rest = idx - 1184;
        if (rest < 32) { flavor = 1; sub = 592 + rest; }
        else           { flavor = 0; sub = 592 + (rest - 32); }
    }
    if (flavor)
        popcount_body(sm, PC_ROW0 + sub, gamma, beta, rmean, rvar, out);
    else
        imma_body(sm, sub, gamma, beta, rmean, rvar, out);
}

// ---------------------------------------------------------------------------
extern "C" void kernel_launch(void* const* d_in, const int* in_sizes, int n_in,
                              void* d_out, int out_size) {
    const float* x     = (const float*)d_in[0];
    const float* wt    = (const float*)d_in[1];
    const float* gamma = (const float*)d_in[2];
    const float* beta  = (const float*)d_in[3];
    const float* rmean = (const float*)d_in[4];
    const float* rvar  = (const float*)d_in[5];
    float* out = (float*)d_out;

    cudaFuncSetAttribute(conv_hybrid_kernel,
                         cudaFuncAttributeMaxDynamicSharedMemorySize, SMEM_DYN);

    pack_xcomb_kernel<<<NB * HH, 512>>>(x);
    pack_ws_kernel<<<9 * COUT, 256>>>(wt);
    pack_wp_kernel<<<72, 256>>>(wt);
    conv_hybrid_kernel<<<PC_BLOCKS + IMMA_BLOCKS, 256, SMEM_DYN>>>(
        gamma, beta, rmean, rvar, out);
}